// round 3
// baseline (speedup 1.0000x reference)
#include <cuda_runtime.h>

#define N 8192
#define THREADS 256
#define GRID 888                      // 148 SMs * 6 resident blocks
#define F4_PER_ROW (N / 4)            // 2048 float4 per row
#define ITERS (F4_PER_ROW / THREADS)  // 8 float4 per thread per row
#define LOG2E 1.44269504088896340736f
#define LN2   0.69314718055994530942f

__device__ float g_partials[GRID];
__device__ int   g_counter;           // zero-init; reset by last block each run

// softplus in log2 units: log2(1 + 2^x) = max(x,0) + log2(1 + 2^(-|x|))
__device__ __forceinline__ float softplus2(float x) {
    float e = exp2f(0.0f - fabsf(x));
    return fmaxf(x, 0.0f) + __log2f(1.0f + e);
}

__global__ void __launch_bounds__(THREADS)
bt_persistent_kernel(const float* __restrict__ win,
                     const float* __restrict__ betas,
                     float* __restrict__ out) {
    const float4* win4 = reinterpret_cast<const float4*>(win);
    const float4* b4   = reinterpret_cast<const float4*>(betas);
    const int tid = threadIdx.x;

    float acc0 = 0.0f, acc1 = 0.0f;

    for (int row = blockIdx.x; row < N; row += GRID) {
        const float bi   = __ldg(betas + row);
        const float nbiL = -bi * LOG2E;
        const float4* wrow = win4 + (size_t)row * F4_PER_ROW;

        #pragma unroll
        for (int k = 0; k < ITERS; k++) {
            const int p = k * THREADS + tid;
            float4 w  = __ldg(wrow + p);
            float4 bj = __ldg(b4 + p);

            float x0 = fmaf(bj.x, LOG2E, nbiL);
            float x1 = fmaf(bj.y, LOG2E, nbiL);
            float x2 = fmaf(bj.z, LOG2E, nbiL);
            float x3 = fmaf(bj.w, LOG2E, nbiL);

            acc0 = fmaf(w.x, softplus2(x0), acc0);
            acc1 = fmaf(w.y, softplus2(x1), acc1);
            acc0 = fmaf(w.z, softplus2(x2), acc0);
            acc1 = fmaf(w.w, softplus2(x3), acc1);
        }

        // Subtract diagonal term (j == row), recomputed with identical FP ops
        // so cancellation against the main-loop term is exact.
        if (tid == 0) {
            float wd = __ldg(win + (size_t)row * N + row);
            float xd = fmaf(bi, LOG2E, nbiL);
            acc0 -= wd * softplus2(xd);
        }
    }

    float acc = acc0 + acc1;

    // block reduction
    #pragma unroll
    for (int off = 16; off > 0; off >>= 1)
        acc += __shfl_xor_sync(0xFFFFFFFFu, acc, off);

    __shared__ float warp_sums[THREADS / 32];
    const int lane = tid & 31;
    const int wid  = tid >> 5;
    if (lane == 0) warp_sums[wid] = acc;
    __syncthreads();

    float blocksum = 0.0f;
    if (wid == 0) {
        float v = (lane < THREADS / 32) ? warp_sums[lane] : 0.0f;
        #pragma unroll
        for (int off = 4; off > 0; off >>= 1)
            v += __shfl_xor_sync(0xFFFFFFFFu, v, off);
        blocksum = v;
    }

    // last-block final reduction (threadfence-reduction pattern, no pre-zeroed out)
    __shared__ bool am_last;
    if (tid == 0) {
        g_partials[blockIdx.x] = blocksum;
        __threadfence();
        int prev = atomicAdd(&g_counter, 1);
        am_last = (prev == GRID - 1);
    }
    __syncthreads();

    if (am_last) {
        float v = 0.0f;
        for (int i = tid; i < GRID; i += THREADS)
            v += g_partials[i];

        #pragma unroll
        for (int off = 16; off > 0; off >>= 1)
            v += __shfl_xor_sync(0xFFFFFFFFu, v, off);
        if (lane == 0) warp_sums[wid] = v;
        __syncthreads();
        if (wid == 0) {
            float t = (lane < THREADS / 32) ? warp_sums[lane] : 0.0f;
            #pragma unroll
            for (int off = 4; off > 0; off >>= 1)
                t += __shfl_xor_sync(0xFFFFFFFFu, t, off);
            if (lane == 0) {
                *out = t * LN2;      // overwrite poison with plain store
                g_counter = 0;       // reset for next graph replay
            }
        }
    }
}

extern "C" void kernel_launch(void* const* d_in, const int* in_sizes, int n_in,
                              void* d_out, int out_size) {
    const float* win   = (const float*)d_in[0];
    const float* betas = (const float*)d_in[1];
    float* out = (float*)d_out;

    bt_persistent_kernel<<<GRID, THREADS>>>(win, betas, out);
}

// round 4
// speedup vs baseline: 1.1141x; 1.1141x over previous
#include <cuda_runtime.h>

#define N 8192
#define THREADS 256
#define BLOCKS_PER_SM 7
#define GRID (148 * BLOCKS_PER_SM)    // 1036: one wave
#define F4_PER_ROW (N / 4)            // 2048 float4 per row
#define ITERS (F4_PER_ROW / THREADS)  // 8 float4 per thread per row
#define LOG2E 1.44269504088896340736f
#define LN2   0.69314718055994530942f

__device__ float g_accum;             // zero-init; reset by last block each run
__device__ int   g_counter;           // zero-init; reset by last block each run

// softplus in log2 units: log2(1 + 2^x) = max(x,0) + log2(1 + 2^(-|x|))
__device__ __forceinline__ float softplus2(float x) {
    float e = exp2f(0.0f - fabsf(x));
    return fmaxf(x, 0.0f) + __log2f(1.0f + e);
}

__global__ void __launch_bounds__(THREADS, BLOCKS_PER_SM)
bt_persistent_kernel(const float* __restrict__ win,
                     const float* __restrict__ betas,
                     float* __restrict__ out) {
    const float4* win4 = reinterpret_cast<const float4*>(win);
    const float4* b4   = reinterpret_cast<const float4*>(betas);
    const int tid = threadIdx.x;

    float acc0 = 0.0f, acc1 = 0.0f;

    #pragma unroll 1
    for (int row = blockIdx.x; row < N; row += GRID) {
        const float bi   = __ldg(betas + row);
        const float nbiL = -bi * LOG2E;
        const float4* wrow = win4 + (size_t)row * F4_PER_ROW;

        #pragma unroll
        for (int k = 0; k < ITERS; k++) {
            const int p = k * THREADS + tid;
            float4 w  = __ldcs(wrow + p);     // streaming: read-once, evict-first
            float4 bj = __ldg(b4 + p);        // L1-resident

            float x0 = fmaf(bj.x, LOG2E, nbiL);
            float x1 = fmaf(bj.y, LOG2E, nbiL);
            float x2 = fmaf(bj.z, LOG2E, nbiL);
            float x3 = fmaf(bj.w, LOG2E, nbiL);

            acc0 = fmaf(w.x, softplus2(x0), acc0);
            acc1 = fmaf(w.y, softplus2(x1), acc1);
            acc0 = fmaf(w.z, softplus2(x2), acc0);
            acc1 = fmaf(w.w, softplus2(x3), acc1);
        }

        // Subtract diagonal term (j == row), recomputed with identical FP ops
        // so cancellation against the main-loop term is exact.
        if (tid == 0) {
            float wd = __ldg(win + (size_t)row * N + row);
            float xd = fmaf(bi, LOG2E, nbiL);
            acc0 -= wd * softplus2(xd);
        }
    }

    float acc = acc0 + acc1;

    // block reduction
    #pragma unroll
    for (int off = 16; off > 0; off >>= 1)
        acc += __shfl_xor_sync(0xFFFFFFFFu, acc, off);

    __shared__ float warp_sums[THREADS / 32];
    const int lane = tid & 31;
    const int wid  = tid >> 5;
    if (lane == 0) warp_sums[wid] = acc;
    __syncthreads();

    // last-block finalization: no pre-zeroed output needed
    if (tid == 0) {
        float v = warp_sums[0];
        #pragma unroll
        for (int i = 1; i < THREADS / 32; i++) v += warp_sums[i];

        atomicAdd(&g_accum, v);
        __threadfence();
        int prev = atomicAdd(&g_counter, 1);
        if (prev == GRID - 1) {
            __threadfence();
            float total = *((volatile float*)&g_accum);
            *out = total * LN2;      // overwrite poison with plain store
            g_accum   = 0.0f;        // reset for next graph replay
            __threadfence();
            g_counter = 0;
        }
    }
}

extern "C" void kernel_launch(void* const* d_in, const int* in_sizes, int n_in,
                              void* d_out, int out_size) {
    const float* win   = (const float*)d_in[0];
    const float* betas = (const float*)d_in[1];
    float* out = (float*)d_out;

    bt_persistent_kernel<<<GRID, THREADS>>>(win, betas, out);
}

// round 5
// speedup vs baseline: 1.2031x; 1.0799x over previous
#include <cuda_runtime.h>

#define N 8192
#define THREADS 256
#define F4_PER_ROW (N / 4)            // 2048 float4 per row
#define ITERS (F4_PER_ROW / THREADS)  // 8 float4 per thread
#define LOG2E 1.44269504088896340736f
#define LN2   0.69314718055994530942f

__device__ float g_accum;             // zero-init; reset by last block each run
__device__ int   g_counter;           // zero-init; reset by last block each run

// softplus in log2 units: log2(1 + 2^x) = max(x,0) + log2(1 + 2^(-|x|))
__device__ __forceinline__ float softplus2(float x) {
    float e = exp2f(0.0f - fabsf(x));
    return fmaxf(x, 0.0f) + __log2f(1.0f + e);
}

__global__ void __launch_bounds__(THREADS)
bt_row_kernel(const float* __restrict__ win,
              const float* __restrict__ betas,
              float* __restrict__ out) {
    const int row = blockIdx.x;
    const float bi   = __ldg(betas + row);
    const float nbiL = -bi * LOG2E;           // block-uniform

    const float4* wrow = reinterpret_cast<const float4*>(win) + (size_t)row * F4_PER_ROW;
    const float4* b4   = reinterpret_cast<const float4*>(betas);

    float acc0 = 0.0f, acc1 = 0.0f;

    #pragma unroll
    for (int k = 0; k < ITERS; k++) {
        const int p = k * THREADS + threadIdx.x;
        float4 w  = __ldg(wrow + p);
        float4 bj = __ldg(b4 + p);

        float x0 = fmaf(bj.x, LOG2E, nbiL);
        float x1 = fmaf(bj.y, LOG2E, nbiL);
        float x2 = fmaf(bj.z, LOG2E, nbiL);
        float x3 = fmaf(bj.w, LOG2E, nbiL);

        acc0 = fmaf(w.x, softplus2(x0), acc0);
        acc1 = fmaf(w.y, softplus2(x1), acc1);
        acc0 = fmaf(w.z, softplus2(x2), acc0);
        acc1 = fmaf(w.w, softplus2(x3), acc1);
    }

    float acc = acc0 + acc1;

    // Remove the diagonal term (j == row), recomputed with identical FP ops so
    // the cancellation is exact.
    if (threadIdx.x == 0) {
        float wd = __ldg(win + (size_t)row * N + row);
        float xd = fmaf(bi, LOG2E, nbiL);
        acc -= wd * softplus2(xd);
    }

    // warp reduction
    #pragma unroll
    for (int off = 16; off > 0; off >>= 1)
        acc += __shfl_xor_sync(0xFFFFFFFFu, acc, off);

    __shared__ float warp_sums[THREADS / 32];
    const int lane = threadIdx.x & 31;
    const int wid  = threadIdx.x >> 5;
    if (lane == 0) warp_sums[wid] = acc;
    __syncthreads();

    // Fused finalization: no separate zero-out kernel needed.
    if (threadIdx.x == 0) {
        float v = warp_sums[0];
        #pragma unroll
        for (int i = 1; i < THREADS / 32; i++) v += warp_sums[i];

        atomicAdd(&g_accum, v);
        __threadfence();
        int prev = atomicAdd(&g_counter, 1);
        if (prev == N - 1) {                  // last block to finish
            __threadfence();
            float total = *((volatile float*)&g_accum);
            *out = total * LN2;               // overwrite poison with plain store
            g_accum = 0.0f;                   // reset for next graph replay
            __threadfence();
            g_counter = 0;
        }
    }
}

extern "C" void kernel_launch(void* const* d_in, const int* in_sizes, int n_in,
                              void* d_out, int out_size) {
    const float* win   = (const float*)d_in[0];
    const float* betas = (const float*)d_in[1];
    float* out = (float*)d_out;

    bt_row_kernel<<<N, THREADS>>>(win, betas, out);
}

// round 6
// speedup vs baseline: 1.3693x; 1.1381x over previous
#include <cuda_runtime.h>

#define N 8192
#define THREADS 256
#define F4_PER_ROW (N / 4)            // 2048 float4 per row
#define ITERS (F4_PER_ROW / THREADS)  // 8 float4 per thread
#define LOG2E 1.44269504088896340736f
#define LN2   0.69314718055994530942f

// softplus in log2 units: log2(1 + 2^x) = max(x,0) + log2(1 + 2^(-|x|))
__device__ __forceinline__ float softplus2(float x) {
    float e = exp2f(0.0f - fabsf(x));
    return fmaxf(x, 0.0f) + __log2f(1.0f + e);
}

__global__ void __launch_bounds__(THREADS, 8)
bt_row_kernel(const float* __restrict__ win,
              const float* __restrict__ betas,
              float* __restrict__ out) {
    const int row = blockIdx.x;
    const float bi   = __ldg(betas + row);
    const float nbiL = -bi * LOG2E;           // block-uniform

    const float4* wrow = reinterpret_cast<const float4*>(win) + (size_t)row * F4_PER_ROW;
    const float4* b4   = reinterpret_cast<const float4*>(betas);

    float acc0 = 0.0f, acc1 = 0.0f;

    #pragma unroll
    for (int k = 0; k < ITERS; k++) {
        const int p = k * THREADS + threadIdx.x;
        float4 w  = __ldcs(wrow + p);         // streaming, zero reuse
        float4 bj = __ldg(b4 + p);            // L1/L2-resident

        float x0 = fmaf(bj.x, LOG2E, nbiL);
        float x1 = fmaf(bj.y, LOG2E, nbiL);
        float x2 = fmaf(bj.z, LOG2E, nbiL);
        float x3 = fmaf(bj.w, LOG2E, nbiL);

        acc0 = fmaf(w.x, softplus2(x0), acc0);
        acc1 = fmaf(w.y, softplus2(x1), acc1);
        acc0 = fmaf(w.z, softplus2(x2), acc0);
        acc1 = fmaf(w.w, softplus2(x3), acc1);
    }

    float acc = acc0 + acc1;

    // Remove the diagonal term (j == row), recomputed with identical FP ops so
    // the cancellation is exact.
    if (threadIdx.x == 0) {
        float wd = __ldg(win + (size_t)row * N + row);
        float xd = fmaf(bi, LOG2E, nbiL);
        acc -= wd * softplus2(xd);
    }

    // warp reduction
    #pragma unroll
    for (int off = 16; off > 0; off >>= 1)
        acc += __shfl_xor_sync(0xFFFFFFFFu, acc, off);

    __shared__ float warp_sums[THREADS / 32];
    const int lane = threadIdx.x & 31;
    const int wid  = threadIdx.x >> 5;
    if (lane == 0) warp_sums[wid] = acc;
    __syncthreads();

    if (wid == 0) {
        float v = (lane < THREADS / 32) ? warp_sums[lane] : 0.0f;
        #pragma unroll
        for (int off = 4; off > 0; off >>= 1)
            v += __shfl_xor_sync(0xFFFFFFFFu, v, off);
        if (lane == 0)
            atomicAdd(out, v * LN2);          // fire-and-forget RED, no fence
    }
}

extern "C" void kernel_launch(void* const* d_in, const int* in_sizes, int n_in,
                              void* d_out, int out_size) {
    const float* win   = (const float*)d_in[0];
    const float* betas = (const float*)d_in[1];
    float* out = (float*)d_out;

    cudaMemsetAsync(out, 0, sizeof(float));   // graph memset node, cheaper than a kernel
    bt_row_kernel<<<N, THREADS>>>(win, betas, out);
}